// round 12
// baseline (speedup 1.0000x reference)
#include <cuda_runtime.h>
#include <cuda_bf16.h>
#include <cfloat>
#include <cstdint>

// Problem constants
#define TOK   8192
#define DIM   7168
#define NEXP  256
#define TOPKG 4
#define TOPK  8
#define RSCALE 2.5f

// GEMM tiling (FFMA2 path)
#define BM 128
#define BN 128
#define BK 16
#define NCH (DIM / BK)            // 448 K-chunks
#define ASTR 132                  // floats per k-row of A panel (128 + 4 pad)
#define A_STAGE_B (BK * ASTR * 4)     // 8448 B
#define BSLOT 80                  // bytes per tx-slot: 8 dup'd pairs (64B) + 16B pad
#define BROWB (16 * BSLOT)        // 1280 B per k-row of B panel
#define B_STAGE_B (BK * BROWB)    // 20480 B
#define STAGEB (A_STAGE_B + B_STAGE_B)  // 28928 B
#define NSTAGE 3
#define SMEM_BYTES (NSTAGE * STAGEB)    // 86784 B

// scratch: bias-added sigmoid scores [T, E]
__device__ float g_scores[(size_t)TOK * NEXP];

// ---------------------------------------------------------------------------
// helpers
// ---------------------------------------------------------------------------
typedef unsigned long long ull;

__device__ __forceinline__ void ffma2(ull& d, ull a, ull b) {
    asm("fma.rn.f32x2 %0, %1, %2, %0;" : "+l"(d) : "l"(a), "l"(b));
}
__device__ __forceinline__ ull dup2(float v) {
    ull d;
    asm("mov.b64 %0, {%1, %1};" : "=l"(d) : "f"(v));
    return d;
}
__device__ __forceinline__ void unpack2(ull d, float& lo, float& hi) {
    asm("mov.b64 {%0, %1}, %2;" : "=f"(lo), "=f"(hi) : "l"(d));
}

// ---------------------------------------------------------------------------
// Kernel 1: exact fp32 GEMM on the FMA pipe via packed fma.rn.f32x2.
// 256 threads (8 warps), thread tile 8(M) x 8(N) = 32 FFMA2 per k-step.
//   A panel: k-major fp32, As[k][m], stride 132 floats (2-way STS ok,
//            LDS.128 broadcast across the 16 tx lanes -> conflict-free).
//   B panel: k-major, each value DUPLICATED into an f32x2 pair at store time;
//            16 tx-slots of 80 B per k-row (20*tx mod 32 distinct banks
//            -> conflict-free LDS.128 across each 8-lane phase).
// Accumulation: one FFMA per output per k, k ascending = serial RN fp32,
// identical numerics to the round-2 kernel that passed (rel_err 5.7e-7).
// ---------------------------------------------------------------------------
__global__ __launch_bounds__(256, 1)
void gemm_f32x2_kernel(const float* __restrict__ X,
                       const float* __restrict__ W,
                       const float* __restrict__ bias,
                       float* __restrict__ S)
{
    extern __shared__ char sm[];
    const int tid = threadIdx.x;
    const int ty  = tid >> 4;          // 0..15 -> rows ty*8 .. ty*8+7
    const int tx  = tid & 15;          // 0..15 -> cols tx*8 .. tx*8+7
    const int m0  = blockIdx.y * BM;
    const int n0  = blockIdx.x * BN;

    // producer coords: float4 element e = tid + i*256 -> row r, quad q
    const int pr = tid >> 2;           // 0..63 (+64 for i=1)
    const int pq = tid & 3;

    ull acc[4][8];
#pragma unroll
    for (int i = 0; i < 4; i++)
#pragma unroll
        for (int j = 0; j < 8; j++) acc[i][j] = 0ull;

    float4 RA[2], RB[2];

    auto ldg = [&](int c) {
        const int k0 = c * BK;
#pragma unroll
        for (int i = 0; i < 2; i++) {
            RA[i] = *reinterpret_cast<const float4*>(
                X + (size_t)(m0 + pr + 64 * i) * DIM + k0 + pq * 4);
            RB[i] = *reinterpret_cast<const float4*>(
                W + (size_t)(n0 + pr + 64 * i) * DIM + k0 + pq * 4);
        }
    };
    auto sts = [&](int s) {
        float* ab = reinterpret_cast<float*>(sm + s * STAGEB);
        char*  bb = sm + s * STAGEB + A_STAGE_B;
#pragma unroll
        for (int i = 0; i < 2; i++) {
            const int r = pr + 64 * i;
            const float va[4] = {RA[i].x, RA[i].y, RA[i].z, RA[i].w};
            const float vb[4] = {RB[i].x, RB[i].y, RB[i].z, RB[i].w};
#pragma unroll
            for (int j = 0; j < 4; j++) {
                ab[(pq * 4 + j) * ASTR + r] = va[j];
                *reinterpret_cast<ull*>(
                    bb + (pq * 4 + j) * BROWB + (r >> 3) * BSLOT + (r & 7) * 8) =
                    dup2(vb[j]);
            }
        }
    };

    // prologue
    ldg(0);
    sts(0);
    ldg(1);

    for (int c = 0; c < NCH; c++) {
        __syncthreads();                       // publish sts(c); free stage (c+1)%3
        if (c + 1 < NCH) sts((c + 1) % NSTAGE);
        if (c + 2 < NCH) ldg(c + 2);

        const char* ap = sm + (c % NSTAGE) * STAGEB;
        const char* bp = ap + A_STAGE_B;

#pragma unroll
        for (int k = 0; k < BK; k++) {
            const ulonglong2* A2 =
                reinterpret_cast<const ulonglong2*>(ap + k * (ASTR * 4) + ty * 32);
            const ulonglong2 a01 = A2[0];      // rows (0,1),(2,3)
            const ulonglong2 a23 = A2[1];      // rows (4,5),(6,7)
            const ulonglong2* B2 =
                reinterpret_cast<const ulonglong2*>(bp + k * BROWB + tx * BSLOT);
            const ulonglong2 b01 = B2[0], b23 = B2[1], b45 = B2[2], b67 = B2[3];
            const ull a[4] = {a01.x, a01.y, a23.x, a23.y};
            const ull b[8] = {b01.x, b01.y, b23.x, b23.y, b45.x, b45.y, b67.x, b67.y};
#pragma unroll
            for (int i = 0; i < 4; i++)
#pragma unroll
                for (int j = 0; j < 8; j++)
                    ffma2(acc[i][j], a[i], b[j]);
        }
    }

    // ---- epilogue: sigmoid + bias -> S
    const int colb = n0 + tx * 8;
    float bs[8];
#pragma unroll
    for (int j = 0; j < 8; j++) bs[j] = bias[colb + j];

#pragma unroll
    for (int mp = 0; mp < 4; mp++) {
        float lo[8], hi[8];
#pragma unroll
        for (int j = 0; j < 8; j++) unpack2(acc[mp][j], lo[j], hi[j]);
        float o0[8], o1[8];
#pragma unroll
        for (int j = 0; j < 8; j++) {
            o0[j] = 1.0f / (1.0f + expf(-lo[j])) + bs[j];
            o1[j] = 1.0f / (1.0f + expf(-hi[j])) + bs[j];
        }
        const int row0 = m0 + ty * 8 + mp * 2;
        float* p0 = S + (size_t)row0 * NEXP + colb;
        float* p1 = p0 + NEXP;
        *reinterpret_cast<float4*>(p0)     = make_float4(o0[0], o0[1], o0[2], o0[3]);
        *reinterpret_cast<float4*>(p0 + 4) = make_float4(o0[4], o0[5], o0[6], o0[7]);
        *reinterpret_cast<float4*>(p1)     = make_float4(o1[0], o1[1], o1[2], o1[3]);
        *reinterpret_cast<float4*>(p1 + 4) = make_float4(o1[4], o1[5], o1[6], o1[7]);
    }
}

// ---------------------------------------------------------------------------
// Kernel 2: per-token gating (unchanged)
// ---------------------------------------------------------------------------
__global__ __launch_bounds__(256)
void gate_topk_kernel(const float* __restrict__ S,
                      float* __restrict__ outW,
                      float* __restrict__ outI)
{
    const unsigned FULL = 0xffffffffu;
    const int warp = threadIdx.x >> 5;
    const int lane = threadIdx.x & 31;
    const int token = blockIdx.x * 8 + warp;
    if (token >= TOK) return;

    float v[8];
    {
        const float4* p = reinterpret_cast<const float4*>(
            S + (size_t)token * NEXP + lane * 8);
        float4 a = p[0], b = p[1];
        v[0]=a.x; v[1]=a.y; v[2]=a.z; v[3]=a.w;
        v[4]=b.x; v[5]=b.y; v[6]=b.z; v[7]=b.w;
    }

    float m1 = -FLT_MAX, m2 = -FLT_MAX;
#pragma unroll
    for (int j = 0; j < 8; j++) {
        float x = v[j];
        if (x > m1) { m2 = m1; m1 = x; }
        else if (x > m2) { m2 = x; }
    }
#pragma unroll
    for (int off = 2; off >= 1; off >>= 1) {
        float o1 = __shfl_down_sync(FULL, m1, off, 4);
        float o2 = __shfl_down_sync(FULL, m2, off, 4);
        float n1 = fmaxf(m1, o1);
        float n2 = fmaxf(fminf(m1, o1), fmaxf(m2, o2));
        m1 = n1; m2 = n2;
    }
    float gscore = m1 + m2;

    const int myg = lane >> 2;
    float mygs = __shfl_sync(FULL, gscore, myg * 4);
    int rank = 0;
#pragma unroll
    for (int g = 0; g < 8; g++) {
        float gs = __shfl_sync(FULL, gscore, g * 4);
        if (gs > mygs || (gs == mygs && g < myg)) rank++;
    }
    bool sel = (rank < TOPKG);

    float w[8];
#pragma unroll
    for (int j = 0; j < 8; j++) w[j] = sel ? v[j] : 0.0f;

    for (int r = 0; r < TOPK; r++) {
        float bv = w[0]; int bi = lane * 8;
#pragma unroll
        for (int j = 1; j < 8; j++) {
            int idx = lane * 8 + j;
            if (w[j] > bv) { bv = w[j]; bi = idx; }
        }
#pragma unroll
        for (int o = 16; o > 0; o >>= 1) {
            float ov = __shfl_xor_sync(FULL, bv, o);
            int   oi = __shfl_xor_sync(FULL, bi, o);
            if (ov > bv || (ov == bv && oi < bi)) { bv = ov; bi = oi; }
        }
        int owner = bi >> 3;
        float orig = 0.f;
        if (lane == owner) {
            orig = v[bi & 7];
            w[bi & 7] = -FLT_MAX;
        }
        orig = __shfl_sync(FULL, orig, owner);
        if (lane == r) {
            outW[(size_t)token * TOPK + r] = orig * RSCALE;
            outI[(size_t)token * TOPK + r] = (float)bi;
        }
    }
}

// ---------------------------------------------------------------------------
extern "C" void kernel_launch(void* const* d_in, const int* in_sizes, int n_in,
                              void* d_out, int out_size)
{
    const float* x    = (const float*)d_in[0];
    const float* wght = (const float*)d_in[1];
    const float* bias = (const float*)d_in[2];
    float* out = (float*)d_out;

    float* scores;
    cudaGetSymbolAddress((void**)&scores, g_scores);

    cudaFuncSetAttribute(gemm_f32x2_kernel,
                         cudaFuncAttributeMaxDynamicSharedMemorySize, SMEM_BYTES);

    dim3 grid(NEXP / BN, TOK / BM);
    gemm_f32x2_kernel<<<grid, 256, SMEM_BYTES>>>(x, wght, bias, scores);

    gate_topk_kernel<<<TOK / 8, 256>>>(scores, out, out + (size_t)TOK * TOPK);
}

// round 14
// speedup vs baseline: 2.1844x; 2.1844x over previous
#include <cuda_runtime.h>
#include <cuda_fp16.h>
#include <cuda_bf16.h>
#include <cfloat>
#include <cstdint>

// Problem constants
#define TOK   8192
#define DIM   7168
#define NEXP  256
#define TOPKG 4
#define TOPK  8
#define RSCALE 2.5f

// GEMM tiling
#define BM 128
#define BN 128
#define BK 32
#define NCH (DIM / BK)          // 224 K-chunks
#define NTHREADS 512            // 16 warps: 4(M) x 4(N), warp tile 32x32
#define ROWB 80                 // bytes per smem panel row: 32 fp16 + 16B pad
#define PANELB (128 * ROWB)     // 10240 B
#define STAGEB (4 * PANELB)     // A0,A1,B0,B1 = 40960 B
#define NSTAGE 3
#define SMEM_BYTES (NSTAGE * STAGEB)   // 122880 B

#define NW4 ((size_t)NEXP * DIM / 4)

// scratch: bias-added sigmoid scores + precomputed W fp16 2-way splits
__device__ float g_scores[(size_t)TOK * NEXP];
__device__ uint2 g_ws[2][NW4];          // each uint2 = 4 fp16

// ---------------------------------------------------------------------------
// helpers
// ---------------------------------------------------------------------------
__device__ __forceinline__ uint32_t smem_u32(const void* p) {
    uint32_t a;
    asm("{ .reg .u64 t; cvta.to.shared.u64 t, %1; cvt.u32.u64 %0, t; }"
        : "=r"(a) : "l"(p));
    return a;
}
__device__ __forceinline__ void ldsm_x4(uint32_t* r, uint32_t addr) {
    asm volatile("ldmatrix.sync.aligned.m8n8.x4.shared.b16 {%0,%1,%2,%3}, [%4];"
                 : "=r"(r[0]), "=r"(r[1]), "=r"(r[2]), "=r"(r[3]) : "r"(addr));
}
__device__ __forceinline__ void mma_f16(float* c, const uint32_t* a, const uint32_t* b) {
    asm volatile(
        "mma.sync.aligned.m16n8k16.row.col.f32.f16.f16.f32 "
        "{%0,%1,%2,%3}, {%4,%5,%6,%7}, {%8,%9}, {%0,%1,%2,%3};"
        : "+f"(c[0]), "+f"(c[1]), "+f"(c[2]), "+f"(c[3])
        : "r"(a[0]), "r"(a[1]), "r"(a[2]), "r"(a[3]), "r"(b[0]), "r"(b[1]));
}
__device__ __forceinline__ void cp_async16(uint32_t saddr, const void* g) {
    asm volatile("cp.async.cg.shared.global [%0], [%1], 16;"
                 :: "r"(saddr), "l"(g) : "memory");
}
#define CP_COMMIT() asm volatile("cp.async.commit_group;" ::: "memory")
#define CP_WAIT1()  asm volatile("cp.async.wait_group 1;" ::: "memory")

__device__ __forceinline__ uint32_t h2u(__half2 x) {
    return *reinterpret_cast<uint32_t*>(&x);
}
// fp16 2-way split of a float4: x = h0 + h1 + r, |r| <= 2^-24 |x|
__device__ __forceinline__ void split2(float4 v, uint2& o0, uint2& o1) {
    __half2 p0 = __floats2half2_rn(v.x, v.y);
    __half2 p1 = __floats2half2_rn(v.z, v.w);
    float2 u0 = __half22float2(p0), u1 = __half22float2(p1);
    __half2 q0 = __floats2half2_rn(v.x - u0.x, v.y - u0.y);
    __half2 q1 = __floats2half2_rn(v.z - u1.x, v.w - u1.y);
    o0 = make_uint2(h2u(p0), h2u(p1));
    o1 = make_uint2(h2u(q0), h2u(q1));
}

// ---------------------------------------------------------------------------
// Kernel 0: precompute W fp16 2-way splits (11 MB -> L2-resident in GEMM)
// ---------------------------------------------------------------------------
__global__ __launch_bounds__(256)
void splitw_kernel(const float* __restrict__ W)
{
    size_t i = (size_t)blockIdx.x * 256 + threadIdx.x;
    if (i < NW4) {
        float4 v = reinterpret_cast<const float4*>(W)[i];
        uint2 a, b;
        split2(v, a, b);
        g_ws[0][i] = a; g_ws[1][i] = b;
    }
}

// ---------------------------------------------------------------------------
// Kernel 1: fp16 2-split 4-term GEMM (mma.sync m16n8k16). A split in-loop,
// B via cp.async from precomputed splits. Per-chunk RN containment.
// 512 threads, 16 warps 4x4, warp tile 32x32.
// ---------------------------------------------------------------------------
__global__ __launch_bounds__(NTHREADS, 1)
void gemm_mma_kernel(const float* __restrict__ X,
                     const float* __restrict__ bias,
                     float* __restrict__ S)
{
    extern __shared__ char sm[];
    const int tid  = threadIdx.x;
    const int wid  = tid >> 5, lane = tid & 31;
    const int g    = lane >> 2, tig = lane & 3;
    const int wm   = wid >> 2,  wn  = wid & 3;     // 4x4 warp grid
    const int m0   = blockIdx.y * BM;
    const int n0   = blockIdx.x * BN;
    const uint32_t sb = smem_u32(sm);

    // ldmatrix per-thread base offsets (within a panel)
    const int t8 = lane >> 3;
    const int r8 = lane & 7;
    const uint32_t a_base =
        (uint32_t)((wm * 32 + (t8 & 1) * 8 + r8) * ROWB + (t8 >> 1) * 16);
    const uint32_t b_base =
        (uint32_t)((wn * 32 + (t8 >> 1) * 8 + r8) * ROWB + (t8 & 1) * 16);

    // A producer coords: element e = tid -> row e>>3, float4 q=e&7
    const int pr = tid >> 3, pq = tid & 7;
    const uint32_t pa_off = (uint32_t)(pr * ROWB + pq * 8);
    // B producer coords: 2 cp.async per thread
    const int br = tid >> 2, bq = tid & 3;
    const uint32_t pb_off = (uint32_t)(br * ROWB + bq * 16);

    float acc[2][4][4];
#pragma unroll
    for (int i = 0; i < 2; i++)
#pragma unroll
        for (int j = 0; j < 4; j++)
#pragma unroll
            for (int k = 0; k < 4; k++) acc[i][j][k] = 0.f;

    float4 R[2];   // A LDG buffer (rows pr, pr+64)

    auto ldg_a = [&](int c) {
        const int k0 = c * BK;
        R[0] = *reinterpret_cast<const float4*>(
            X + (size_t)(m0 + pr) * DIM + k0 + pq * 4);
        R[1] = *reinterpret_cast<const float4*>(
            X + (size_t)(m0 + pr + 64) * DIM + k0 + pq * 4);
    };
    auto sts_a = [&](int s) {
        char* ab = sm + s * STAGEB;
#pragma unroll
        for (int i = 0; i < 2; i++) {
            uint2 o0, o1;
            split2(R[i], o0, o1);
            const uint32_t off = pa_off + (uint32_t)(64 * i) * ROWB;
            *reinterpret_cast<uint2*>(ab + off)          = o0;
            *reinterpret_cast<uint2*>(ab + PANELB + off) = o1;
        }
    };
    auto cpb = [&](int c, int s) {
        const int k0 = c * BK;
        const uint32_t st = sb + s * STAGEB + 2 * PANELB;
#pragma unroll
        for (int p = 0; p < 2; p++)
            cp_async16(st + p * PANELB + pb_off,
                       (const __half*)g_ws[p] +
                           (size_t)(n0 + br) * DIM + k0 + bq * 8);
    };

    // prologue
    ldg_a(0);
    sts_a(0);
    ldg_a(1);
    cpb(0, 0); CP_COMMIT();
    cpb(1, 1); CP_COMMIT();

    for (int c = 0; c < NCH; c++) {
        CP_WAIT1();                  // B chunk c landed
        __syncthreads();             // A stores for c visible; old stages free
        if (c + 1 < NCH) sts_a((c + 1) % NSTAGE);
        if (c + 2 < NCH) { ldg_a(c + 2); cpb(c + 2, (c + 2) % NSTAGE); }
        CP_COMMIT();                 // keep FIFO group indexing

        const uint32_t stage = sb + (c % NSTAGE) * STAGEB;
        const uint32_t apan = stage;
        const uint32_t bpan = stage + 2 * PANELB;

        float la[2][4][4];
#pragma unroll
        for (int a = 0; a < 2; a++)
#pragma unroll
            for (int b = 0; b < 4; b++)
#pragma unroll
                for (int k = 0; k < 4; k++) la[a][b][k] = 0.f;

#pragma unroll
        for (int ks = 0; ks < 2; ks++) {
            const uint32_t ko = (uint32_t)(ks * 32);
            uint32_t Bf[2][2][4];
#pragma unroll
            for (int j = 0; j < 2; j++)
#pragma unroll
                for (int p = 0; p < 2; p++)
                    ldsm_x4(Bf[j][p],
                            bpan + (uint32_t)j * PANELB + b_base + p * (16 * ROWB) + ko);

#pragma unroll
            for (int i = 0; i < 2; i++) {
                uint32_t Af[2][4];
#pragma unroll
                for (int mt = 0; mt < 2; mt++)
                    ldsm_x4(Af[mt],
                            apan + (uint32_t)i * PANELB + a_base + mt * (16 * ROWB) + ko);
#pragma unroll
                for (int j = 0; j < 2; j++) {
#pragma unroll
                    for (int mt = 0; mt < 2; mt++)
#pragma unroll
                        for (int nt = 0; nt < 4; nt++)
                            mma_f16(la[mt][nt], Af[mt],
                                    &Bf[j][nt >> 1][(nt & 1) * 2]);
                }
            }
        }
        // RN fold (containment of TC rounding)
#pragma unroll
        for (int mt = 0; mt < 2; mt++)
#pragma unroll
            for (int nt = 0; nt < 4; nt++)
#pragma unroll
                for (int k = 0; k < 4; k++)
                    acc[mt][nt][k] += la[mt][nt][k];
    }

    // ---- epilogue: sigmoid + bias -> S
#pragma unroll
    for (int mt = 0; mt < 2; mt++) {
        const int row0 = m0 + wm * 32 + mt * 16 + g;
#pragma unroll
        for (int nt = 0; nt < 4; nt++) {
            const int ncol = n0 + wn * 32 + nt * 8 + tig * 2;
            const float b0 = bias[ncol], b1 = bias[ncol + 1];
            float2 v0, v1;
            v0.x = 1.0f / (1.0f + expf(-acc[mt][nt][0])) + b0;
            v0.y = 1.0f / (1.0f + expf(-acc[mt][nt][1])) + b1;
            v1.x = 1.0f / (1.0f + expf(-acc[mt][nt][2])) + b0;
            v1.y = 1.0f / (1.0f + expf(-acc[mt][nt][3])) + b1;
            *reinterpret_cast<float2*>(S + (size_t)row0 * NEXP + ncol) = v0;
            *reinterpret_cast<float2*>(S + (size_t)(row0 + 8) * NEXP + ncol) = v1;
        }
    }
}

// ---------------------------------------------------------------------------
// Kernel 2: per-token gating (unchanged)
// ---------------------------------------------------------------------------
__global__ __launch_bounds__(256)
void gate_topk_kernel(const float* __restrict__ S,
                      float* __restrict__ outW,
                      float* __restrict__ outI)
{
    const unsigned FULL = 0xffffffffu;
    const int warp = threadIdx.x >> 5;
    const int lane = threadIdx.x & 31;
    const int token = blockIdx.x * 8 + warp;
    if (token >= TOK) return;

    float v[8];
    {
        const float4* p = reinterpret_cast<const float4*>(
            S + (size_t)token * NEXP + lane * 8);
        float4 a = p[0], b = p[1];
        v[0]=a.x; v[1]=a.y; v[2]=a.z; v[3]=a.w;
        v[4]=b.x; v[5]=b.y; v[6]=b.z; v[7]=b.w;
    }

    float m1 = -FLT_MAX, m2 = -FLT_MAX;
#pragma unroll
    for (int j = 0; j < 8; j++) {
        float x = v[j];
        if (x > m1) { m2 = m1; m1 = x; }
        else if (x > m2) { m2 = x; }
    }
#pragma unroll
    for (int off = 2; off >= 1; off >>= 1) {
        float o1 = __shfl_down_sync(FULL, m1, off, 4);
        float o2 = __shfl_down_sync(FULL, m2, off, 4);
        float n1 = fmaxf(m1, o1);
        float n2 = fmaxf(fminf(m1, o1), fmaxf(m2, o2));
        m1 = n1; m2 = n2;
    }
    float gscore = m1 + m2;

    const int myg = lane >> 2;
    float mygs = __shfl_sync(FULL, gscore, myg * 4);
    int rank = 0;
#pragma unroll
    for (int g = 0; g < 8; g++) {
        float gs = __shfl_sync(FULL, gscore, g * 4);
        if (gs > mygs || (gs == mygs && g < myg)) rank++;
    }
    bool sel = (rank < TOPKG);

    float w[8];
#pragma unroll
    for (int j = 0; j < 8; j++) w[j] = sel ? v[j] : 0.0f;

    for (int r = 0; r < TOPK; r++) {
        float bv = w[0]; int bi = lane * 8;
#pragma unroll
        for (int j = 1; j < 8; j++) {
            int idx = lane * 8 + j;
            if (w[j] > bv) { bv = w[j]; bi = idx; }
        }
#pragma unroll
        for (int o = 16; o > 0; o >>= 1) {
            float ov = __shfl_xor_sync(FULL, bv, o);
            int   oi = __shfl_xor_sync(FULL, bi, o);
            if (ov > bv || (ov == bv && oi < bi)) { bv = ov; bi = oi; }
        }
        int owner = bi >> 3;
        float orig = 0.f;
        if (lane == owner) {
            orig = v[bi & 7];
            w[bi & 7] = -FLT_MAX;
        }
        orig = __shfl_sync(FULL, orig, owner);
        if (lane == r) {
            outW[(size_t)token * TOPK + r] = orig * RSCALE;
            outI[(size_t)token * TOPK + r] = (float)bi;
        }
    }
}

// ---------------------------------------------------------------------------
extern "C" void kernel_launch(void* const* d_in, const int* in_sizes, int n_in,
                              void* d_out, int out_size)
{
    const float* x    = (const float*)d_in[0];
    const float* wght = (const float*)d_in[1];
    const float* bias = (const float*)d_in[2];
    float* out = (float*)d_out;

    float* scores;
    cudaGetSymbolAddress((void**)&scores, g_scores);

    cudaFuncSetAttribute(gemm_mma_kernel,
                         cudaFuncAttributeMaxDynamicSharedMemorySize, SMEM_BYTES);

    splitw_kernel<<<(int)((NW4 + 255) / 256), 256>>>(wght);

    dim3 grid(NEXP / BN, TOK / BM);
    gemm_mma_kernel<<<grid, NTHREADS, SMEM_BYTES>>>(x, bias, scores);

    gate_topk_kernel<<<TOK / 8, 256>>>(scores, out, out + (size_t)TOK * TOPK);
}

// round 15
// speedup vs baseline: 2.5704x; 1.1767x over previous
#include <cuda_runtime.h>
#include <cuda_fp16.h>
#include <cuda_bf16.h>
#include <cfloat>
#include <cstdint>

// Problem constants
#define TOK   8192
#define DIM   7168
#define NEXP  256
#define TOPKG 4
#define TOPK  8
#define RSCALE 2.5f

// GEMM tiling
#define BM 128
#define BN 128
#define BK 32
#define NCH (DIM / BK)          // 224 K-chunks
#define NTHREADS 512            // 16 warps: 4(M) x 4(N), warp tile 32x32
#define ROWB 80                 // bytes per smem panel row: 32 fp16 + 16B pad
#define PANELB (128 * ROWB)     // 10240 B
#define STAGEB (4 * PANELB)     // A0,A1,B0,B1 = 40960 B
#define NSTAGE 3
#define SMEM_BYTES (NSTAGE * STAGEB)   // 122880 B

#define NW4 ((size_t)NEXP * DIM / 4)

// scratch: bias-added sigmoid scores + precomputed W fp16 2-way splits
__device__ float g_scores[(size_t)TOK * NEXP];
__device__ uint2 g_ws[2][NW4];          // each uint2 = 4 fp16

// ---------------------------------------------------------------------------
// helpers
// ---------------------------------------------------------------------------
__device__ __forceinline__ uint32_t smem_u32(const void* p) {
    uint32_t a;
    asm("{ .reg .u64 t; cvta.to.shared.u64 t, %1; cvt.u32.u64 %0, t; }"
        : "=r"(a) : "l"(p));
    return a;
}
__device__ __forceinline__ void ldsm_x4(uint32_t* r, uint32_t addr) {
    asm volatile("ldmatrix.sync.aligned.m8n8.x4.shared.b16 {%0,%1,%2,%3}, [%4];"
                 : "=r"(r[0]), "=r"(r[1]), "=r"(r[2]), "=r"(r[3]) : "r"(addr));
}
__device__ __forceinline__ void mma_f16(float* c, const uint32_t* a, const uint32_t* b) {
    asm volatile(
        "mma.sync.aligned.m16n8k16.row.col.f32.f16.f16.f32 "
        "{%0,%1,%2,%3}, {%4,%5,%6,%7}, {%8,%9}, {%0,%1,%2,%3};"
        : "+f"(c[0]), "+f"(c[1]), "+f"(c[2]), "+f"(c[3])
        : "r"(a[0]), "r"(a[1]), "r"(a[2]), "r"(a[3]), "r"(b[0]), "r"(b[1]));
}
__device__ __forceinline__ void cp_async16(uint32_t saddr, const void* g) {
    asm volatile("cp.async.cg.shared.global [%0], [%1], 16;"
                 :: "r"(saddr), "l"(g) : "memory");
}
#define CP_COMMIT() asm volatile("cp.async.commit_group;" ::: "memory")
#define CP_WAIT1()  asm volatile("cp.async.wait_group 1;" ::: "memory")

__device__ __forceinline__ uint32_t h2u(__half2 x) {
    return *reinterpret_cast<uint32_t*>(&x);
}
// fp16 2-way split of a float4: x = h0 + h1 + r, |r| <= 2^-24 |x|
__device__ __forceinline__ void split2(float4 v, uint2& o0, uint2& o1) {
    __half2 p0 = __floats2half2_rn(v.x, v.y);
    __half2 p1 = __floats2half2_rn(v.z, v.w);
    float2 u0 = __half22float2(p0), u1 = __half22float2(p1);
    __half2 q0 = __floats2half2_rn(v.x - u0.x, v.y - u0.y);
    __half2 q1 = __floats2half2_rn(v.z - u1.x, v.w - u1.y);
    o0 = make_uint2(h2u(p0), h2u(p1));
    o1 = make_uint2(h2u(q0), h2u(q1));
}

// ---------------------------------------------------------------------------
// Kernel 0: precompute W fp16 2-way splits (11 MB -> L2-resident in GEMM)
// ---------------------------------------------------------------------------
__global__ __launch_bounds__(256)
void splitw_kernel(const float* __restrict__ W)
{
    size_t i = (size_t)blockIdx.x * 256 + threadIdx.x;
    if (i < NW4) {
        float4 v = reinterpret_cast<const float4*>(W)[i];
        uint2 a, b;
        split2(v, a, b);
        g_ws[0][i] = a; g_ws[1][i] = b;
    }
}

// ---------------------------------------------------------------------------
// Kernel 1: fp16 2-split 3-term GEMM (mma.sync m16n8k16): h0h0 + h0h1 + h1h0.
// Dropped h1h1 term contributes ~5e-6 logit noise (below fp32-reorder scale).
// A split in-loop, B via cp.async from precomputed splits. Per-chunk RN
// containment. 512 threads, 16 warps 4x4, warp tile 32x32.
// ---------------------------------------------------------------------------
__global__ __launch_bounds__(NTHREADS, 1)
void gemm_mma_kernel(const float* __restrict__ X,
                     const float* __restrict__ bias,
                     float* __restrict__ S)
{
    extern __shared__ char sm[];
    const int tid  = threadIdx.x;
    const int wid  = tid >> 5, lane = tid & 31;
    const int g    = lane >> 2, tig = lane & 3;
    const int wm   = wid >> 2,  wn  = wid & 3;     // 4x4 warp grid
    const int m0   = blockIdx.y * BM;
    const int n0   = blockIdx.x * BN;
    const uint32_t sb = smem_u32(sm);

    // ldmatrix per-thread base offsets (within a panel)
    const int t8 = lane >> 3;
    const int r8 = lane & 7;
    const uint32_t a_base =
        (uint32_t)((wm * 32 + (t8 & 1) * 8 + r8) * ROWB + (t8 >> 1) * 16);
    const uint32_t b_base =
        (uint32_t)((wn * 32 + (t8 >> 1) * 8 + r8) * ROWB + (t8 & 1) * 16);

    // A producer coords: element e = tid -> row e>>3, float4 q=e&7
    const int pr = tid >> 3, pq = tid & 7;
    const uint32_t pa_off = (uint32_t)(pr * ROWB + pq * 8);
    // B producer coords: 2 cp.async per thread
    const int br = tid >> 2, bq = tid & 3;
    const uint32_t pb_off = (uint32_t)(br * ROWB + bq * 16);

    float acc[2][4][4];
#pragma unroll
    for (int i = 0; i < 2; i++)
#pragma unroll
        for (int j = 0; j < 4; j++)
#pragma unroll
            for (int k = 0; k < 4; k++) acc[i][j][k] = 0.f;

    float4 R[2];   // A LDG buffer (rows pr, pr+64)

    auto ldg_a = [&](int c) {
        const int k0 = c * BK;
        R[0] = *reinterpret_cast<const float4*>(
            X + (size_t)(m0 + pr) * DIM + k0 + pq * 4);
        R[1] = *reinterpret_cast<const float4*>(
            X + (size_t)(m0 + pr + 64) * DIM + k0 + pq * 4);
    };
    auto sts_a = [&](int s) {
        char* ab = sm + s * STAGEB;
#pragma unroll
        for (int i = 0; i < 2; i++) {
            uint2 o0, o1;
            split2(R[i], o0, o1);
            const uint32_t off = pa_off + (uint32_t)(64 * i) * ROWB;
            *reinterpret_cast<uint2*>(ab + off)          = o0;
            *reinterpret_cast<uint2*>(ab + PANELB + off) = o1;
        }
    };
    auto cpb = [&](int c, int s) {
        const int k0 = c * BK;
        const uint32_t st = sb + s * STAGEB + 2 * PANELB;
#pragma unroll
        for (int p = 0; p < 2; p++)
            cp_async16(st + p * PANELB + pb_off,
                       (const __half*)g_ws[p] +
                           (size_t)(n0 + br) * DIM + k0 + bq * 8);
    };

    // prologue
    ldg_a(0);
    sts_a(0);
    ldg_a(1);
    cpb(0, 0); CP_COMMIT();
    cpb(1, 1); CP_COMMIT();

    for (int c = 0; c < NCH; c++) {
        CP_WAIT1();                  // B chunk c landed
        __syncthreads();             // A stores for c visible; old stages free
        if (c + 1 < NCH) sts_a((c + 1) % NSTAGE);
        if (c + 2 < NCH) { ldg_a(c + 2); cpb(c + 2, (c + 2) % NSTAGE); }
        CP_COMMIT();                 // keep FIFO group indexing

        const uint32_t stage = sb + (c % NSTAGE) * STAGEB;
        const uint32_t apan = stage;
        const uint32_t bpan = stage + 2 * PANELB;

        float la[2][4][4];
#pragma unroll
        for (int a = 0; a < 2; a++)
#pragma unroll
            for (int b = 0; b < 4; b++)
#pragma unroll
                for (int k = 0; k < 4; k++) la[a][b][k] = 0.f;

#pragma unroll
        for (int ks = 0; ks < 2; ks++) {
            const uint32_t ko = (uint32_t)(ks * 32);
            uint32_t Bf[2][2][4];
#pragma unroll
            for (int j = 0; j < 2; j++)
#pragma unroll
                for (int p = 0; p < 2; p++)
                    ldsm_x4(Bf[j][p],
                            bpan + (uint32_t)j * PANELB + b_base + p * (16 * ROWB) + ko);

#pragma unroll
            for (int i = 0; i < 2; i++) {
                uint32_t Af[2][4];
#pragma unroll
                for (int mt = 0; mt < 2; mt++)
                    ldsm_x4(Af[mt],
                            apan + (uint32_t)i * PANELB + a_base + mt * (16 * ROWB) + ko);
#pragma unroll
                for (int j = 0; j < 2; j++) {
                    if (i + j <= 1) {      // 3 terms: h0h0, h0h1, h1h0
#pragma unroll
                        for (int mt = 0; mt < 2; mt++)
#pragma unroll
                            for (int nt = 0; nt < 4; nt++)
                                mma_f16(la[mt][nt], Af[mt],
                                        &Bf[j][nt >> 1][(nt & 1) * 2]);
                    }
                }
            }
        }
        // RN fold (containment of TC rounding)
#pragma unroll
        for (int mt = 0; mt < 2; mt++)
#pragma unroll
            for (int nt = 0; nt < 4; nt++)
#pragma unroll
                for (int k = 0; k < 4; k++)
                    acc[mt][nt][k] += la[mt][nt][k];
    }

    // ---- epilogue: sigmoid + bias -> S
#pragma unroll
    for (int mt = 0; mt < 2; mt++) {
        const int row0 = m0 + wm * 32 + mt * 16 + g;
#pragma unroll
        for (int nt = 0; nt < 4; nt++) {
            const int ncol = n0 + wn * 32 + nt * 8 + tig * 2;
            const float b0 = bias[ncol], b1 = bias[ncol + 1];
            float2 v0, v1;
            v0.x = 1.0f / (1.0f + expf(-acc[mt][nt][0])) + b0;
            v0.y = 1.0f / (1.0f + expf(-acc[mt][nt][1])) + b1;
            v1.x = 1.0f / (1.0f + expf(-acc[mt][nt][2])) + b0;
            v1.y = 1.0f / (1.0f + expf(-acc[mt][nt][3])) + b1;
            *reinterpret_cast<float2*>(S + (size_t)row0 * NEXP + ncol) = v0;
            *reinterpret_cast<float2*>(S + (size_t)(row0 + 8) * NEXP + ncol) = v1;
        }
    }
}

// ---------------------------------------------------------------------------
// Kernel 2: per-token gating (unchanged)
// ---------------------------------------------------------------------------
__global__ __launch_bounds__(256)
void gate_topk_kernel(const float* __restrict__ S,
                      float* __restrict__ outW,
                      float* __restrict__ outI)
{
    const unsigned FULL = 0xffffffffu;
    const int warp = threadIdx.x >> 5;
    const int lane = threadIdx.x & 31;
    const int token = blockIdx.x * 8 + warp;
    if (token >= TOK) return;

    float v[8];
    {
        const float4* p = reinterpret_cast<const float4*>(
            S + (size_t)token * NEXP + lane * 8);
        float4 a = p[0], b = p[1];
        v[0]=a.x; v[1]=a.y; v[2]=a.z; v[3]=a.w;
        v[4]=b.x; v[5]=b.y; v[6]=b.z; v[7]=b.w;
    }

    float m1 = -FLT_MAX, m2 = -FLT_MAX;
#pragma unroll
    for (int j = 0; j < 8; j++) {
        float x = v[j];
        if (x > m1) { m2 = m1; m1 = x; }
        else if (x > m2) { m2 = x; }
    }
#pragma unroll
    for (int off = 2; off >= 1; off >>= 1) {
        float o1 = __shfl_down_sync(FULL, m1, off, 4);
        float o2 = __shfl_down_sync(FULL, m2, off, 4);
        float n1 = fmaxf(m1, o1);
        float n2 = fmaxf(fminf(m1, o1), fmaxf(m2, o2));
        m1 = n1; m2 = n2;
    }
    float gscore = m1 + m2;

    const int myg = lane >> 2;
    float mygs = __shfl_sync(FULL, gscore, myg * 4);
    int rank = 0;
#pragma unroll
    for (int g = 0; g < 8; g++) {
        float gs = __shfl_sync(FULL, gscore, g * 4);
        if (gs > mygs || (gs == mygs && g < myg)) rank++;
    }
    bool sel = (rank < TOPKG);

    float w[8];
#pragma unroll
    for (int j = 0; j < 8; j++) w[j] = sel ? v[j] : 0.0f;

    for (int r = 0; r < TOPK; r++) {
        float bv = w[0]; int bi = lane * 8;
#pragma unroll
        for (int j = 1; j < 8; j++) {
            int idx = lane * 8 + j;
            if (w[j] > bv) { bv = w[j]; bi = idx; }
        }
#pragma unroll
        for (int o = 16; o > 0; o >>= 1) {
            float ov = __shfl_xor_sync(FULL, bv, o);
            int   oi = __shfl_xor_sync(FULL, bi, o);
            if (ov > bv || (ov == bv && oi < bi)) { bv = ov; bi = oi; }
        }
        int owner = bi >> 3;
        float orig = 0.f;
        if (lane == owner) {
            orig = v[bi & 7];
            w[bi & 7] = -FLT_MAX;
        }
        orig = __shfl_sync(FULL, orig, owner);
        if (lane == r) {
            outW[(size_t)token * TOPK + r] = orig * RSCALE;
            outI[(size_t)token * TOPK + r] = (float)bi;
        }
    }
}

// ---------------------------------------------------------------------------
extern "C" void kernel_launch(void* const* d_in, const int* in_sizes, int n_in,
                              void* d_out, int out_size)
{
    const float* x    = (const float*)d_in[0];
    const float* wght = (const float*)d_in[1];
    const float* bias = (const float*)d_in[2];
    float* out = (float*)d_out;

    float* scores;
    cudaGetSymbolAddress((void**)&scores, g_scores);

    cudaFuncSetAttribute(gemm_mma_kernel,
                         cudaFuncAttributeMaxDynamicSharedMemorySize, SMEM_BYTES);

    splitw_kernel<<<(int)((NW4 + 255) / 256), 256>>>(wght);

    dim3 grid(NEXP / BN, TOK / BM);
    gemm_mma_kernel<<<grid, NTHREADS, SMEM_BYTES>>>(x, bias, scores);

    gate_topk_kernel<<<TOK / 8, 256>>>(scores, out, out + (size_t)TOK * TOPK);
}